// round 15
// baseline (speedup 1.0000x reference)
#include <cuda_runtime.h>
#include <cstdint>

// MaSIF geodesic conv, GB300 sm_103a — packed-gather round.
// vs round 11/13 (211us):
//  (1) E table replaced by P-table of pre-packed pairs P[v][x]=(E[x+1],E[x])
//      (u64), XOR-swizzled x^(v&31) on a 32-u64 row: ND theta-gather becomes
//      2 aligned LDS.64 per vertex (was 4 scalar LDS + 2 pk2 movs).
//  (2) conv remapped i=tid>>6, j=tid&63 (active j<40): every warp is
//      single-feature, desc LDS.128 broadcasts back to 1 phase.
// All arithmetic unchanged -> bit-identical output expected.
//
// Th[v][k][t] = E_v[((k+K0_v)&15) - t + 15]; E_v built with 4 exps/vertex.
// ND:   (25 x 128) @ (128 x 256) in smem, FFMA2 accumulators.
// conv: desc @ W_i + b_i (W via L1/L2), max over 16 rotations, relu.

#define NV    128
#define NBINS 80
#define EPSF  1e-5f
#define NDS   272        // ND row stride (≡16 mod 32 banks)

// smem float offsets (per-CTA total 73344 bytes -> 3 CTAs/SM)
#define OFF_A     0          // 25 x 128            (dead after ND)
#define OFF_P     3200       // 128 x 32 u64 = 8192 floats (dead after ND)
#define OFF_DESC  0          // 4 x 80 x 20 = 6400 — ALIASES A/P (divide phase)
#define OFF_ND    11392      // 25 x 272 = 6800
#define OFF_K0    18192      // 128 ints (16B aligned: 72768B)
#define OFF_MUR   18320      // 5
#define OFF_ISR   18328      // 5
#define SMEM_FLOATS 18336    // 73344 bytes

typedef unsigned long long u64;

__device__ __forceinline__ u64 pk2(float lo, float hi) {
    u64 r;
    asm("mov.b64 %0, {%1, %2};" : "=l"(r) : "f"(lo), "f"(hi));
    return r;
}
__device__ __forceinline__ void fma2(u64& d, u64 a, u64 b) {
    asm("fma.rn.f32x2 %0, %1, %2, %0;" : "+l"(d) : "l"(a), "l"(b));
}
__device__ __forceinline__ float2 upk2(u64 v) {
    float2 f;
    asm("mov.b64 {%0, %1}, %2;" : "=f"(f.x), "=f"(f.y) : "l"(v));
    return f;
}

// One ND tile: NC columns starting at C0; lane covers kt0 = 4q .. 4q+3.
template<int C0, int NC>
__device__ __forceinline__ void nd_block(const float* __restrict__ s_A,
                                         const u64* __restrict__ s_P,
                                         const int* __restrict__ s_K0,
                                         float* __restrict__ s_ND,
                                         int q)
{
    const int kt0   = q * 4;
    const int kg    = q >> 2;            // shared by the lane's 4 kt
    const int boff1 = 15 - 4 * (q & 3) - 1;   // (base-1) = m + boff1
    const int boff3 = boff1 - 2;              // (base-3)

    u64 acc2[NC][2];
    #pragma unroll
    for (int c = 0; c < NC; c++) { acc2[c][0] = 0ull; acc2[c][1] = 0ull; }

    #pragma unroll 1
    for (int v = 0; v < NV; v += 4) {
        float4 a4[NC];
        #pragma unroll
        for (int c = 0; c < NC; c++)
            a4[c] = *(const float4*)&s_A[(C0 + c) * NV + v];

        int4 k4 = *(const int4*)&s_K0[v];          // warp-uniform broadcast
        int kvals[4] = {k4.x, k4.y, k4.z, k4.w};

        #pragma unroll
        for (int jv = 0; jv < 4; jv++) {
            const u64* Pp = s_P + ((v + jv) << 5);
            int vx = (v + jv) & 31;                // warp-uniform
            int m  = (kg + kvals[jv]) & 15;
            u64 tv01 = Pp[(m + boff1) ^ vx];       // (E[base], E[base-1])
            u64 tv23 = Pp[(m + boff3) ^ vx];       // (E[base-2], E[base-3])
            #pragma unroll
            for (int c = 0; c < NC; c++) {
                float a = (jv == 0) ? a4[c].x : (jv == 1) ? a4[c].y
                        : (jv == 2) ? a4[c].z : a4[c].w;
                u64 aa = pk2(a, a);
                fma2(acc2[c][0], aa, tv01);
                fma2(acc2[c][1], aa, tv23);
            }
        }
    }
    #pragma unroll
    for (int c = 0; c < NC; c++) {
        float2 lo = upk2(acc2[c][0]);
        float2 hi = upk2(acc2[c][1]);
        float4 o;
        o.x = lo.x; o.y = lo.y; o.z = hi.x; o.w = hi.y;
        *(float4*)&s_ND[(C0 + c) * NDS + kt0] = o;
    }
}

__global__ __launch_bounds__(256, 3)
void masif_kernel(const float* __restrict__ rho,
                  const float* __restrict__ theta,
                  const float* __restrict__ feat,
                  const float* __restrict__ mask,
                  const float* __restrict__ mu_rho,
                  const float* __restrict__ sigma_rho,
                  const float* __restrict__ mu_theta,
                  const float* __restrict__ sigma_theta,
                  const float* __restrict__ W,
                  const float* __restrict__ bias,
                  float* __restrict__ out)
{
    extern __shared__ float sm[];
    float* s_A    = sm + OFF_A;
    u64*   s_P    = (u64*)(sm + OFF_P);
    float* s_ND   = sm + OFF_ND;
    float* s_desc = sm + OFF_DESC;   // aliases A/P (safe: written after ND)
    int*   s_K0   = (int*)(sm + OFF_K0);
    float* s_mur  = sm + OFF_MUR;
    float* s_isr  = sm + OFF_ISR;

    const int tid = threadIdx.x;
    const int n   = blockIdx.x;
    const float two_pi = 6.2831855f;           // float32(2*pi)
    const float step   = two_pi / 16.0f;

    // ---- prologue: small tables ----
    if (tid < 5) {
        s_mur[tid] = mu_rho[tid * 16];
        float s = sigma_rho[tid * 16];
        s_isr[tid] = 1.0f / (s * s + EPSF);
    }
    float st0 = sigma_theta[0];
    const float ist = 1.0f / (st0 * st0 + EPSF);
    __syncthreads();

    // ---- A build (threads 0..127) and P build (threads 128..255) ----
    if (tid < 128) {
        int v = tid;
        float rv = rho[n * NV + v];
        float m  = mask[n * NV + v];
        float4 f4 = ((const float4*)feat)[n * NV + v];
        #pragma unroll
        for (int r = 0; r < 5; r++) {
            float d = rv - s_mur[r];
            float e = __expf(-d * d * s_isr[r]) * m;
            s_A[(20 + r) * NV + v] = e;
            s_A[(0 * 5 + r) * NV + v] = e * f4.x;
            s_A[(1 * 5 + r) * NV + v] = e * f4.y;
            s_A[(2 * 5 + r) * NV + v] = e * f4.z;
            s_A[(3 * 5 + r) * NV + v] = e * f4.w;
        }
    } else {
        // P tables: packed pairs P[x] = (E[x+1], E[x]), x = 0..29, 4 exps/vertex.
        int v = tid - 128;
        float th = theta[n * NV + v];
        float kf = floorf(th * (16.0f / two_pi));
        int K0 = (int)kf;
        if (K0 > 15) K0 = 15;
        if (K0 < 0)  K0 = 0;
        float u  = th - (float)K0 * step;
        float E0 = __expf(-ist * u * u);
        float q  = __expf(-ist * step * step);
        float q2 = q * q;
        float rr = __expf(-2.0f * ist * u * step);
        float ri = __expf( 2.0f * ist * u * step);
        u64* Pr = s_P + (v << 5);
        int vx = v & 31;
        // up-chain: E[15+j]; P[14+j] = (E[15+j], E[14+j])
        float e = E0, mlt = rr * q, prev = E0;
        #pragma unroll
        for (int j = 1; j <= 15; j++) {
            e *= mlt;
            Pr[(14 + j) ^ vx] = pk2(e, prev);
            prev = e; mlt *= q2;
        }
        // down-chain: E[15-j]; P[15-j] = (E[16-j], E[15-j])
        e = E0; mlt = ri * q; prev = E0;
        #pragma unroll
        for (int j = 1; j <= 15; j++) {
            e *= mlt;
            Pr[(15 - j) ^ vx] = pk2(prev, e);
            prev = e; mlt *= q2;
        }
        s_K0[v] = K0;
    }
    __syncthreads();

    // ---- ND matmul: (25 x 128) @ (128 x 256) -> s_ND (stride 272), FFMA2 ----
    // 8 warps: col-groups (7,6,6,6) x 2 kt-halves; lane owns 4 kt.
    {
        int w  = tid >> 5;
        int q  = ((w & 1) << 5) | (tid & 31);   // 0..63
        int cg = w >> 1;                        // 0..3, warp-uniform
        if (cg == 0)      nd_block<0, 7>(s_A, s_P, s_K0, s_ND, q);
        else if (cg == 1) nd_block<7, 6>(s_A, s_P, s_K0, s_ND, q);
        else if (cg == 2) nd_block<13, 6>(s_A, s_P, s_K0, s_ND, q);
        else              nd_block<19, 6>(s_A, s_P, s_K0, s_ND, q);
    }
    __syncthreads();

    // ---- divide: shared denominators, 1 rcp per (b, k); 320 items / 256 thr ----
    // (writes s_desc, which aliases the now-dead A/P region)
    for (int idx = tid; idx < 320; idx += 256) {
        int kq = idx / 80;               // 0..3
        int b  = idx - kq * 80;          // 0..79
        int r  = b >> 4, t = b & 15;
        const float* Dp = s_ND + (20 + r) * NDS + t;
        float rc[4];
        #pragma unroll
        for (int kk = 0; kk < 4; kk++)
            rc[kk] = __fdividef(1.0f, Dp[(kq * 4 + kk) * 16] + EPSF);
        #pragma unroll
        for (int i = 0; i < 4; i++) {
            const float* Np = s_ND + (i * 5 + r) * NDS + t;
            float4 o;
            o.x = Np[(kq * 4 + 0) * 16] * rc[0];
            o.y = Np[(kq * 4 + 1) * 16] * rc[1];
            o.z = Np[(kq * 4 + 2) * 16] * rc[2];
            o.w = Np[(kq * 4 + 3) * 16] * rc[3];
            *(float4*)&s_desc[(i * NBINS + b) * 20 + kq * 4] = o;
        }
    }
    __syncthreads();

    // ---- conv + max over 16 rot + relu: warp-aligned features ----
    // i = tid>>6 (warp-uniform), j = tid&63, active j<40 -> 2 bins/thread.
    // W via L2 (coalesced float2); desc LDS.128 broadcasts (1 phase/warp).
    {
        int i = tid >> 6;
        int j = tid & 63;
        if (j < 40) {
            int b0 = j * 2;

            float2 bv = *(const float2*)&bias[i * NBINS + b0];
            u64 accA[8], accB[8];
            u64 bA = pk2(bv.x, bv.x), bB = pk2(bv.y, bv.y);
            #pragma unroll
            for (int jj = 0; jj < 8; jj++) { accA[jj] = bA; accB[jj] = bB; }

            const float* wcol  = W + i * NBINS * NBINS + b0;
            const float* dbase = s_desc + i * NBINS * 20;
            #pragma unroll 4
            for (int bp = 0; bp < NBINS; bp++) {
                float2 wv = *(const float2*)&wcol[bp * NBINS];
                u64 wa = pk2(wv.x, wv.x);
                u64 wb = pk2(wv.y, wv.y);
                const float* dp = dbase + bp * 20;             // 16B-aligned
                ulonglong2 q0 = *(const ulonglong2*)(dp);        // k0..k3
                ulonglong2 q1 = *(const ulonglong2*)(dp + 4);    // k4..k7
                ulonglong2 q2 = *(const ulonglong2*)(dp + 8);    // k8..k11
                ulonglong2 q3 = *(const ulonglong2*)(dp + 12);   // k12..k15
                fma2(accA[0], q0.x, wa); fma2(accB[0], q0.x, wb);
                fma2(accA[1], q0.y, wa); fma2(accB[1], q0.y, wb);
                fma2(accA[2], q1.x, wa); fma2(accB[2], q1.x, wb);
                fma2(accA[3], q1.y, wa); fma2(accB[3], q1.y, wb);
                fma2(accA[4], q2.x, wa); fma2(accB[4], q2.x, wb);
                fma2(accA[5], q2.y, wa); fma2(accB[5], q2.y, wb);
                fma2(accA[6], q3.x, wa); fma2(accB[6], q3.x, wb);
                fma2(accA[7], q3.y, wa); fma2(accB[7], q3.y, wb);
            }
            float mA = -3.4e38f, mB = -3.4e38f;
            #pragma unroll
            for (int jj = 0; jj < 8; jj++) {
                float2 pa = upk2(accA[jj]);
                float2 pb = upk2(accB[jj]);
                mA = fmaxf(mA, fmaxf(pa.x, pa.y));
                mB = fmaxf(mB, fmaxf(pb.x, pb.y));
            }
            float2 o;
            o.x = fmaxf(mA, 0.0f);
            o.y = fmaxf(mB, 0.0f);
            *(float2*)&out[(n * 4 + i) * NBINS + b0] = o;
        }
    }
}

extern "C" void kernel_launch(void* const* d_in, const int* in_sizes, int n_in,
                              void* d_out, int out_size)
{
    const float* rho         = (const float*)d_in[0];
    const float* theta       = (const float*)d_in[1];
    const float* feat        = (const float*)d_in[2];
    const float* mask        = (const float*)d_in[3];
    const float* mu_rho      = (const float*)d_in[4];
    const float* sigma_rho   = (const float*)d_in[5];
    const float* mu_theta    = (const float*)d_in[6];
    const float* sigma_theta = (const float*)d_in[7];
    const float* W           = (const float*)d_in[8];
    const float* bias        = (const float*)d_in[9];
    float* out = (float*)d_out;

    const size_t smem_bytes = SMEM_FLOATS * sizeof(float);   // 73344
    cudaFuncSetAttribute(masif_kernel,
                         cudaFuncAttributeMaxDynamicSharedMemorySize,
                         (int)smem_bytes);

    masif_kernel<<<4096, 256, smem_bytes>>>(
        rho, theta, feat, mask, mu_rho, sigma_rho, mu_theta, sigma_theta,
        W, bias, out);
}

// round 16
// speedup vs baseline: 1.0726x; 1.0726x over previous
#include <cuda_runtime.h>
#include <cstdint>

// MaSIF geodesic conv, GB300 sm_103a — recovery round.
// Base = round-11/13 kernel (211us, best known): scalar E-table gathers with
// immediate offsets (P-table XOR variant REVERTED — it moved the bottleneck
// to integer issue, alu 20->39%). Single retained change vs round 13:
// conv remapped i=tid>>6, j=tid&63 (active j<40) so every conv warp is
// single-feature -> desc LDS.128 broadcasts are 1-phase.
//
// Th[v][k][t] = E_v[((k+K0_v)&15) - t + 15]; E_v built with 4 exps/vertex.
// ND:   (25 x 128) @ (128 x 256) in smem, FFMA2 accumulators.
// conv: desc @ W_i + b_i (W via L1/L2), max over 16 rotations, relu.

#define NV    128
#define NBINS 80
#define EPSF  1e-5f
#define NDS   272        // ND row stride (≡16 mod 32 banks)

// smem float offsets (per-CTA total 57472 bytes -> 3 CTAs/SM)
#define OFF_A     0          // 25 x 128   (dead after ND)
#define OFF_E     3200       // 128 x 33   (dead after ND)
#define OFF_DESC  0          // 4 x 80 x 20 = 6400 — ALIASES A/E (divide phase)
#define OFF_ND    7424       // 25 x 272 = 6800
#define OFF_K0    14224      // 128 ints (16B aligned)
#define OFF_MUR   14352      // 5
#define OFF_ISR   14360      // 5
#define SMEM_FLOATS 14368    // 57472 bytes

typedef unsigned long long u64;

__device__ __forceinline__ u64 pk2(float lo, float hi) {
    u64 r;
    asm("mov.b64 %0, {%1, %2};" : "=l"(r) : "f"(lo), "f"(hi));
    return r;
}
__device__ __forceinline__ void fma2(u64& d, u64 a, u64 b) {
    asm("fma.rn.f32x2 %0, %1, %2, %0;" : "+l"(d) : "l"(a), "l"(b));
}
__device__ __forceinline__ float2 upk2(u64 v) {
    float2 f;
    asm("mov.b64 {%0, %1}, %2;" : "=f"(f.x), "=f"(f.y) : "l"(v));
    return f;
}

// One ND tile: NC columns starting at C0; lane covers kt0 = 4q .. 4q+3.
template<int C0, int NC>
__device__ __forceinline__ void nd_block(const float* __restrict__ s_A,
                                         const float* __restrict__ s_E,
                                         const int* __restrict__ s_K0,
                                         float* __restrict__ s_ND,
                                         int q)
{
    const int kt0  = q * 4;
    const int kg   = q >> 2;            // shared by the lane's 4 kt
    const int boff = 15 - 4 * (q & 3);  // base = ((kg+K0)&15) + boff

    u64 acc2[NC][2];
    #pragma unroll
    for (int c = 0; c < NC; c++) { acc2[c][0] = 0ull; acc2[c][1] = 0ull; }

    #pragma unroll 1
    for (int v = 0; v < NV; v += 4) {
        float4 a4[NC];
        #pragma unroll
        for (int c = 0; c < NC; c++)
            a4[c] = *(const float4*)&s_A[(C0 + c) * NV + v];

        int4 k4 = *(const int4*)&s_K0[v];          // warp-uniform broadcast
        int kvals[4] = {k4.x, k4.y, k4.z, k4.w};

        #pragma unroll
        for (int jv = 0; jv < 4; jv++) {
            const float* Ep = s_E + (v + jv) * 33;
            int base = ((kg + kvals[jv]) & 15) + boff;
            u64 tv01 = pk2(Ep[base],     Ep[base - 1]);
            u64 tv23 = pk2(Ep[base - 2], Ep[base - 3]);
            #pragma unroll
            for (int c = 0; c < NC; c++) {
                float a = (jv == 0) ? a4[c].x : (jv == 1) ? a4[c].y
                        : (jv == 2) ? a4[c].z : a4[c].w;
                u64 aa = pk2(a, a);
                fma2(acc2[c][0], aa, tv01);
                fma2(acc2[c][1], aa, tv23);
            }
        }
    }
    #pragma unroll
    for (int c = 0; c < NC; c++) {
        float2 lo = upk2(acc2[c][0]);
        float2 hi = upk2(acc2[c][1]);
        float4 o;
        o.x = lo.x; o.y = lo.y; o.z = hi.x; o.w = hi.y;
        *(float4*)&s_ND[(C0 + c) * NDS + kt0] = o;
    }
}

__global__ __launch_bounds__(256, 3)
void masif_kernel(const float* __restrict__ rho,
                  const float* __restrict__ theta,
                  const float* __restrict__ feat,
                  const float* __restrict__ mask,
                  const float* __restrict__ mu_rho,
                  const float* __restrict__ sigma_rho,
                  const float* __restrict__ mu_theta,
                  const float* __restrict__ sigma_theta,
                  const float* __restrict__ W,
                  const float* __restrict__ bias,
                  float* __restrict__ out)
{
    extern __shared__ float sm[];
    float* s_A    = sm + OFF_A;
    float* s_E    = sm + OFF_E;
    float* s_ND   = sm + OFF_ND;
    float* s_desc = sm + OFF_DESC;   // aliases A/E (safe: written after ND)
    int*   s_K0   = (int*)(sm + OFF_K0);
    float* s_mur  = sm + OFF_MUR;
    float* s_isr  = sm + OFF_ISR;

    const int tid = threadIdx.x;
    const int n   = blockIdx.x;
    const float two_pi = 6.2831855f;           // float32(2*pi)
    const float step   = two_pi / 16.0f;

    // ---- prologue: small tables ----
    if (tid < 5) {
        s_mur[tid] = mu_rho[tid * 16];
        float s = sigma_rho[tid * 16];
        s_isr[tid] = 1.0f / (s * s + EPSF);
    }
    float st0 = sigma_theta[0];
    const float ist = 1.0f / (st0 * st0 + EPSF);
    __syncthreads();

    // ---- A build (threads 0..127) and E build (threads 128..255) ----
    if (tid < 128) {
        int v = tid;
        float rv = rho[n * NV + v];
        float m  = mask[n * NV + v];
        float4 f4 = ((const float4*)feat)[n * NV + v];
        #pragma unroll
        for (int r = 0; r < 5; r++) {
            float d = rv - s_mur[r];
            float e = __expf(-d * d * s_isr[r]) * m;
            s_A[(20 + r) * NV + v] = e;
            s_A[(0 * 5 + r) * NV + v] = e * f4.x;
            s_A[(1 * 5 + r) * NV + v] = e * f4.y;
            s_A[(2 * 5 + r) * NV + v] = e * f4.z;
            s_A[(3 * 5 + r) * NV + v] = e * f4.w;
        }
    } else {
        // E tables: 31 theta-Gaussian values per vertex, 4 exps each
        int v = tid - 128;
        float th = theta[n * NV + v];
        float kf = floorf(th * (16.0f / two_pi));
        int K0 = (int)kf;
        if (K0 > 15) K0 = 15;
        if (K0 < 0)  K0 = 0;
        float u  = th - (float)K0 * step;
        float E0 = __expf(-ist * u * u);
        float q  = __expf(-ist * step * step);
        float q2 = q * q;
        float rr = __expf(-2.0f * ist * u * step);
        float ri = __expf( 2.0f * ist * u * step);
        float* Ep = s_E + v * 33;
        Ep[15] = E0;
        float e = E0, mlt = rr * q;
        #pragma unroll
        for (int j = 1; j <= 15; j++) { e *= mlt; Ep[15 + j] = e; mlt *= q2; }
        e = E0; mlt = ri * q;
        #pragma unroll
        for (int j = 1; j <= 15; j++) { e *= mlt; Ep[15 - j] = e; mlt *= q2; }
        s_K0[v] = K0;
    }
    __syncthreads();

    // ---- ND matmul: (25 x 128) @ (128 x 256) -> s_ND (stride 272), FFMA2 ----
    // 8 warps: col-groups (7,6,6,6) x 2 kt-halves; lane owns 4 kt.
    {
        int w  = tid >> 5;
        int q  = ((w & 1) << 5) | (tid & 31);   // 0..63
        int cg = w >> 1;                        // 0..3, warp-uniform
        if (cg == 0)      nd_block<0, 7>(s_A, s_E, s_K0, s_ND, q);
        else if (cg == 1) nd_block<7, 6>(s_A, s_E, s_K0, s_ND, q);
        else if (cg == 2) nd_block<13, 6>(s_A, s_E, s_K0, s_ND, q);
        else              nd_block<19, 6>(s_A, s_E, s_K0, s_ND, q);
    }
    __syncthreads();

    // ---- divide: shared denominators, 1 rcp per (b, k); 320 items / 256 thr ----
    // (writes s_desc, which aliases the now-dead A/E region)
    for (int idx = tid; idx < 320; idx += 256) {
        int kq = idx / 80;               // 0..3
        int b  = idx - kq * 80;          // 0..79
        int r  = b >> 4, t = b & 15;
        const float* Dp = s_ND + (20 + r) * NDS + t;
        float rc[4];
        #pragma unroll
        for (int kk = 0; kk < 4; kk++)
            rc[kk] = __fdividef(1.0f, Dp[(kq * 4 + kk) * 16] + EPSF);
        #pragma unroll
        for (int i = 0; i < 4; i++) {
            const float* Np = s_ND + (i * 5 + r) * NDS + t;
            float4 o;
            o.x = Np[(kq * 4 + 0) * 16] * rc[0];
            o.y = Np[(kq * 4 + 1) * 16] * rc[1];
            o.z = Np[(kq * 4 + 2) * 16] * rc[2];
            o.w = Np[(kq * 4 + 3) * 16] * rc[3];
            *(float4*)&s_desc[(i * NBINS + b) * 20 + kq * 4] = o;
        }
    }
    __syncthreads();

    // ---- conv + max over 16 rot + relu: warp-aligned features ----
    // i = tid>>6 (warp-uniform), j = tid&63, active j<40 -> 2 bins/thread.
    // W via L2 (coalesced float2); desc LDS.128 broadcasts (1 phase/warp).
    {
        int i = tid >> 6;
        int j = tid & 63;
        if (j < 40) {
            int b0 = j * 2;

            float2 bv = *(const float2*)&bias[i * NBINS + b0];
            u64 accA[8], accB[8];
            u64 bA = pk2(bv.x, bv.x), bB = pk2(bv.y, bv.y);
            #pragma unroll
            for (int jj = 0; jj < 8; jj++) { accA[jj] = bA; accB[jj] = bB; }

            const float* wcol  = W + i * NBINS * NBINS + b0;
            const float* dbase = s_desc + i * NBINS * 20;
            #pragma unroll 4
            for (int bp = 0; bp < NBINS; bp++) {
                float2 wv = *(const float2*)&wcol[bp * NBINS];
                u64 wa = pk2(wv.x, wv.x);
                u64 wb = pk2(wv.y, wv.y);
                const float* dp = dbase + bp * 20;             // 16B-aligned
                ulonglong2 q0 = *(const ulonglong2*)(dp);        // k0..k3
                ulonglong2 q1 = *(const ulonglong2*)(dp + 4);    // k4..k7
                ulonglong2 q2 = *(const ulonglong2*)(dp + 8);    // k8..k11
                ulonglong2 q3 = *(const ulonglong2*)(dp + 12);   // k12..k15
                fma2(accA[0], q0.x, wa); fma2(accB[0], q0.x, wb);
                fma2(accA[1], q0.y, wa); fma2(accB[1], q0.y, wb);
                fma2(accA[2], q1.x, wa); fma2(accB[2], q1.x, wb);
                fma2(accA[3], q1.y, wa); fma2(accB[3], q1.y, wb);
                fma2(accA[4], q2.x, wa); fma2(accB[4], q2.x, wb);
                fma2(accA[5], q2.y, wa); fma2(accB[5], q2.y, wb);
                fma2(accA[6], q3.x, wa); fma2(accB[6], q3.x, wb);
                fma2(accA[7], q3.y, wa); fma2(accB[7], q3.y, wb);
            }
            float mA = -3.4e38f, mB = -3.4e38f;
            #pragma unroll
            for (int jj = 0; jj < 8; jj++) {
                float2 pa = upk2(accA[jj]);
                float2 pb = upk2(accB[jj]);
                mA = fmaxf(mA, fmaxf(pa.x, pa.y));
                mB = fmaxf(mB, fmaxf(pb.x, pb.y));
            }
            float2 o;
            o.x = fmaxf(mA, 0.0f);
            o.y = fmaxf(mB, 0.0f);
            *(float2*)&out[(n * 4 + i) * NBINS + b0] = o;
        }
    }
}

extern "C" void kernel_launch(void* const* d_in, const int* in_sizes, int n_in,
                              void* d_out, int out_size)
{
    const float* rho         = (const float*)d_in[0];
    const float* theta       = (const float*)d_in[1];
    const float* feat        = (const float*)d_in[2];
    const float* mask        = (const float*)d_in[3];
    const float* mu_rho      = (const float*)d_in[4];
    const float* sigma_rho   = (const float*)d_in[5];
    const float* mu_theta    = (const float*)d_in[6];
    const float* sigma_theta = (const float*)d_in[7];
    const float* W           = (const float*)d_in[8];
    const float* bias        = (const float*)d_in[9];
    float* out = (float*)d_out;

    const size_t smem_bytes = SMEM_FLOATS * sizeof(float);   // 57472
    cudaFuncSetAttribute(masif_kernel,
                         cudaFuncAttributeMaxDynamicSharedMemorySize,
                         (int)smem_bytes);

    masif_kernel<<<4096, 256, smem_bytes>>>(
        rho, theta, feat, mask, mu_rho, sigma_rho, mu_theta, sigma_theta,
        W, bias, out);
}

// round 17
// speedup vs baseline: 1.1956x; 1.1146x over previous
#include <cuda_runtime.h>
#include <cstdint>

// MaSIF geodesic conv, GB300 sm_103a — c-pair FFMA2 round.
// Base = round-13 kernel (211us best). Single change: ND accumulators pack the
// COLUMN dimension (c, c+1) instead of kt, with A stored as u64 column-pairs
// A2[cp][v] (26 cols, col 25 = zero pad). This removes the per-(jv,c)
// pk2(a,a) replication mov (NC+2 -> 4 pk2 per jv), ~4.5K warp-instr/CTA.
// Accumulation order per (c,kt) unchanged -> bit-identical output.
// Conv restored to round-13 form (5 full warps, i = tid/40) after round 15
// showed idle-lane warps pay full issue cost.
//
// Th[v][k][t] = E_v[((k+K0_v)&15) - t + 15]; E_v built with 4 exps/vertex.
// ND:   (26 x 128) @ (128 x 256) in smem, FFMA2, row 25 is padding.
// conv: desc @ W_i + b_i (W via L1/L2), max over 16 rotations, relu.

#define NV    128
#define NBINS 80
#define EPSF  1e-5f
#define NDS   272        // ND row stride (≡16 mod 32 banks)

// smem float offsets (per-CTA total 59072 bytes -> 3 CTAs/SM)
#define OFF_A2    0          // 13 x 128 u64 = 3328 floats (dead after ND)
#define OFF_E     3328       // 128 x 33 = 4224           (dead after ND)
#define OFF_DESC  0          // 4 x 80 x 20 = 6400 — ALIASES A2/E (divide phase)
#define OFF_ND    7552       // 26 x 272 = 7072
#define OFF_K0    14624      // 128 ints (16B aligned)
#define OFF_MUR   14752      // 5
#define OFF_ISR   14760      // 5
#define SMEM_FLOATS 14768    // 59072 bytes

typedef unsigned long long u64;

__device__ __forceinline__ u64 pk2(float lo, float hi) {
    u64 r;
    asm("mov.b64 %0, {%1, %2};" : "=l"(r) : "f"(lo), "f"(hi));
    return r;
}
__device__ __forceinline__ void fma2(u64& d, u64 a, u64 b) {
    asm("fma.rn.f32x2 %0, %1, %2, %0;" : "+l"(d) : "l"(a), "l"(b));
}
__device__ __forceinline__ float2 upk2(u64 v) {
    float2 f;
    asm("mov.b64 {%0, %1}, %2;" : "=f"(f.x), "=f"(f.y) : "l"(v));
    return f;
}

// One ND tile: NCP column-pairs starting at pair CP0; lane covers kt0=4q..4q+3.
// acc[cp][j] packs columns (2(CP0+cp), 2(CP0+cp)+1) for kt = kt0+j.
template<int CP0, int NCP>
__device__ __forceinline__ void nd_block(const u64* __restrict__ s_A2,
                                         const float* __restrict__ s_E,
                                         const int* __restrict__ s_K0,
                                         float* __restrict__ s_ND,
                                         int q)
{
    const int kt0  = q * 4;
    const int kg   = q >> 2;            // shared by the lane's 4 kt
    const int boff = 15 - 4 * (q & 3);  // base = ((kg+K0)&15) + boff

    u64 acc[NCP][4];
    #pragma unroll
    for (int cp = 0; cp < NCP; cp++)
        #pragma unroll
        for (int j = 0; j < 4; j++) acc[cp][j] = 0ull;

    #pragma unroll 1
    for (int v = 0; v < NV; v += 4) {
        ulonglong2 a01[NCP], a23[NCP];   // (v,v+1), (v+2,v+3) column-pairs
        #pragma unroll
        for (int cp = 0; cp < NCP; cp++) {
            const u64* Ap = &s_A2[(CP0 + cp) * NV + v];
            a01[cp] = *(const ulonglong2*)(Ap);
            a23[cp] = *(const ulonglong2*)(Ap + 2);
        }

        int4 k4 = *(const int4*)&s_K0[v];          // warp-uniform broadcast
        int kvals[4] = {k4.x, k4.y, k4.z, k4.w};

        #pragma unroll
        for (int jv = 0; jv < 4; jv++) {
            const float* Ep = s_E + (v + jv) * 33;
            int base = ((kg + kvals[jv]) & 15) + boff;
            float t0 = Ep[base];
            float t1 = Ep[base - 1];
            float t2 = Ep[base - 2];
            float t3 = Ep[base - 3];
            u64 p0 = pk2(t0, t0);
            u64 p1 = pk2(t1, t1);
            u64 p2 = pk2(t2, t2);
            u64 p3 = pk2(t3, t3);
            #pragma unroll
            for (int cp = 0; cp < NCP; cp++) {
                u64 av = (jv == 0) ? a01[cp].x : (jv == 1) ? a01[cp].y
                       : (jv == 2) ? a23[cp].x : a23[cp].y;
                fma2(acc[cp][0], av, p0);
                fma2(acc[cp][1], av, p1);
                fma2(acc[cp][2], av, p2);
                fma2(acc[cp][3], av, p3);
            }
        }
    }
    #pragma unroll
    for (int cp = 0; cp < NCP; cp++) {
        float2 u0 = upk2(acc[cp][0]);
        float2 u1 = upk2(acc[cp][1]);
        float2 u2 = upk2(acc[cp][2]);
        float2 u3 = upk2(acc[cp][3]);
        int c = 2 * (CP0 + cp);
        float4 lo; lo.x = u0.x; lo.y = u1.x; lo.z = u2.x; lo.w = u3.x;
        float4 hi; hi.x = u0.y; hi.y = u1.y; hi.z = u2.y; hi.w = u3.y;
        *(float4*)&s_ND[c * NDS + kt0]       = lo;
        *(float4*)&s_ND[(c + 1) * NDS + kt0] = hi;
    }
}

__global__ __launch_bounds__(256, 3)
void masif_kernel(const float* __restrict__ rho,
                  const float* __restrict__ theta,
                  const float* __restrict__ feat,
                  const float* __restrict__ mask,
                  const float* __restrict__ mu_rho,
                  const float* __restrict__ sigma_rho,
                  const float* __restrict__ mu_theta,
                  const float* __restrict__ sigma_theta,
                  const float* __restrict__ W,
                  const float* __restrict__ bias,
                  float* __restrict__ out)
{
    extern __shared__ float sm[];
    u64*   s_A2   = (u64*)(sm + OFF_A2);
    float* s_E    = sm + OFF_E;
    float* s_ND   = sm + OFF_ND;
    float* s_desc = sm + OFF_DESC;   // aliases A2/E (safe: written after ND)
    int*   s_K0   = (int*)(sm + OFF_K0);
    float* s_mur  = sm + OFF_MUR;
    float* s_isr  = sm + OFF_ISR;

    const int tid = threadIdx.x;
    const int n   = blockIdx.x;
    const float two_pi = 6.2831855f;           // float32(2*pi)
    const float step   = two_pi / 16.0f;

    // ---- prologue: small tables ----
    if (tid < 5) {
        s_mur[tid] = mu_rho[tid * 16];
        float s = sigma_rho[tid * 16];
        s_isr[tid] = 1.0f / (s * s + EPSF);
    }
    float st0 = sigma_theta[0];
    const float ist = 1.0f / (st0 * st0 + EPSF);
    __syncthreads();

    // ---- A2 build (threads 0..127) and E build (threads 128..255) ----
    if (tid < 128) {
        int v = tid;
        float rv = rho[n * NV + v];
        float m  = mask[n * NV + v];
        float4 f4 = ((const float4*)feat)[n * NV + v];
        float col[26];
        #pragma unroll
        for (int r = 0; r < 5; r++) {
            float d = rv - s_mur[r];
            float e = __expf(-d * d * s_isr[r]) * m;
            col[20 + r] = e;
            col[0 * 5 + r] = e * f4.x;
            col[1 * 5 + r] = e * f4.y;
            col[2 * 5 + r] = e * f4.z;
            col[3 * 5 + r] = e * f4.w;
        }
        col[25] = 0.0f;                       // pad column
        #pragma unroll
        for (int cp = 0; cp < 13; cp++)
            s_A2[cp * NV + v] = pk2(col[2 * cp], col[2 * cp + 1]);
    } else {
        // E tables: 31 theta-Gaussian values per vertex, 4 exps each
        int v = tid - 128;
        float th = theta[n * NV + v];
        float kf = floorf(th * (16.0f / two_pi));
        int K0 = (int)kf;
        if (K0 > 15) K0 = 15;
        if (K0 < 0)  K0 = 0;
        float u  = th - (float)K0 * step;
        float E0 = __expf(-ist * u * u);
        float q  = __expf(-ist * step * step);
        float q2 = q * q;
        float rr = __expf(-2.0f * ist * u * step);
        float ri = __expf( 2.0f * ist * u * step);
        float* Ep = s_E + v * 33;
        Ep[15] = E0;
        float e = E0, mlt = rr * q;
        #pragma unroll
        for (int j = 1; j <= 15; j++) { e *= mlt; Ep[15 + j] = e; mlt *= q2; }
        e = E0; mlt = ri * q;
        #pragma unroll
        for (int j = 1; j <= 15; j++) { e *= mlt; Ep[15 - j] = e; mlt *= q2; }
        s_K0[v] = K0;
    }
    __syncthreads();

    // ---- ND matmul: (26 x 128) @ (128 x 256) -> s_ND (stride 272), FFMA2 ----
    // 8 warps: pair-groups (4,3,3,3) x 2 kt-halves; lane owns 4 kt.
    {
        int w  = tid >> 5;
        int q  = ((w & 1) << 5) | (tid & 31);   // 0..63
        int cg = w >> 1;                        // 0..3, warp-uniform
        if (cg == 0)      nd_block<0, 4>(s_A2, s_E, s_K0, s_ND, q);
        else if (cg == 1) nd_block<4, 3>(s_A2, s_E, s_K0, s_ND, q);
        else if (cg == 2) nd_block<7, 3>(s_A2, s_E, s_K0, s_ND, q);
        else              nd_block<10, 3>(s_A2, s_E, s_K0, s_ND, q);
    }
    __syncthreads();

    // ---- divide: shared denominators, 1 rcp per (b, k); 320 items / 256 thr ----
    // (writes s_desc, which aliases the now-dead A2/E region)
    for (int idx = tid; idx < 320; idx += 256) {
        int kq = idx / 80;               // 0..3
        int b  = idx - kq * 80;          // 0..79
        int r  = b >> 4, t = b & 15;
        const float* Dp = s_ND + (20 + r) * NDS + t;
        float rc[4];
        #pragma unroll
        for (int kk = 0; kk < 4; kk++)
            rc[kk] = __fdividef(1.0f, Dp[(kq * 4 + kk) * 16] + EPSF);
        #pragma unroll
        for (int i = 0; i < 4; i++) {
            const float* Np = s_ND + (i * 5 + r) * NDS + t;
            float4 o;
            o.x = Np[(kq * 4 + 0) * 16] * rc[0];
            o.y = Np[(kq * 4 + 1) * 16] * rc[1];
            o.z = Np[(kq * 4 + 2) * 16] * rc[2];
            o.w = Np[(kq * 4 + 3) * 16] * rc[3];
            *(float4*)&s_desc[(i * NBINS + b) * 20 + kq * 4] = o;
        }
    }
    __syncthreads();

    // ---- conv + max over 16 rot + relu: 160 threads (5 full warps) ----
    // Round-13 mapping: i = tid/40. W via L2 (coalesced float2);
    // desc LDS.128 broadcasts feed both bins.
    if (tid < 160) {
        int i  = tid / 40;
        int j  = tid - i * 40;
        int b0 = j * 2;

        float2 bv = *(const float2*)&bias[i * NBINS + b0];
        u64 accA[8], accB[8];
        u64 bA = pk2(bv.x, bv.x), bB = pk2(bv.y, bv.y);
        #pragma unroll
        for (int jj = 0; jj < 8; jj++) { accA[jj] = bA; accB[jj] = bB; }

        const float* wcol  = W + i * NBINS * NBINS + b0;
        const float* dbase = s_desc + i * NBINS * 20;
        #pragma unroll 4
        for (int bp = 0; bp < NBINS; bp++) {
            float2 wv = *(const float2*)&wcol[bp * NBINS];
            u64 wa = pk2(wv.x, wv.x);
            u64 wb = pk2(wv.y, wv.y);
            const float* dp = dbase + bp * 20;             // 16B-aligned
            ulonglong2 q0 = *(const ulonglong2*)(dp);        // k0..k3
            ulonglong2 q1 = *(const ulonglong2*)(dp + 4);    // k4..k7
            ulonglong2 q2 = *(const ulonglong2*)(dp + 8);    // k8..k11
            ulonglong2 q3 = *(const ulonglong2*)(dp + 12);   // k12..k15
            fma2(accA[0], q0.x, wa); fma2(accB[0], q0.x, wb);
            fma2(accA[1], q0.y, wa); fma2(accB[1], q0.y, wb);
            fma2(accA[2], q1.x, wa); fma2(accB[2], q1.x, wb);
            fma2(accA[3], q1.y, wa); fma2(accB[3], q1.y, wb);
            fma2(accA[4], q2.x, wa); fma2(accB[4], q2.x, wb);
            fma2(accA[5], q2.y, wa); fma2(accB[5], q2.y, wb);
            fma2(accA[6], q3.x, wa); fma2(accB[6], q3.x, wb);
            fma2(accA[7], q3.y, wa); fma2(accB[7], q3.y, wb);
        }
        float mA = -3.4e38f, mB = -3.4e38f;
        #pragma unroll
        for (int jj = 0; jj < 8; jj++) {
            float2 pa = upk2(accA[jj]);
            float2 pb = upk2(accB[jj]);
            mA = fmaxf(mA, fmaxf(pa.x, pa.y));
            mB = fmaxf(mB, fmaxf(pb.x, pb.y));
        }
        float2 o;
        o.x = fmaxf(mA, 0.0f);
        o.y = fmaxf(mB, 0.0f);
        *(float2*)&out[(n * 4 + i) * NBINS + b0] = o;
    }
}

extern "C" void kernel_launch(void* const* d_in, const int* in_sizes, int n_in,
                              void* d_out, int out_size)
{
    const float* rho         = (const float*)d_in[0];
    const float* theta       = (const float*)d_in[1];
    const float* feat        = (const float*)d_in[2];
    const float* mask        = (const float*)d_in[3];
    const float* mu_rho      = (const float*)d_in[4];
    const float* sigma_rho   = (const float*)d_in[5];
    const float* mu_theta    = (const float*)d_in[6];
    const float* sigma_theta = (const float*)d_in[7];
    const float* W           = (const float*)d_in[8];
    const float* bias        = (const float*)d_in[9];
    float* out = (float*)d_out;

    const size_t smem_bytes = SMEM_FLOATS * sizeof(float);   // 59072
    cudaFuncSetAttribute(masif_kernel,
                         cudaFuncAttributeMaxDynamicSharedMemorySize,
                         (int)smem_bytes);

    masif_kernel<<<4096, 256, smem_bytes>>>(
        rho, theta, feat, mask, mu_rho, sigma_rho, mu_theta, sigma_theta,
        W, bias, out);
}